// round 3
// baseline (speedup 1.0000x reference)
#include <cuda_runtime.h>
#include <math.h>
#include <float.h>

#define NH 8
#define SEQ 4096
#define DH 128
#define LQ 64
#define VTOPK 1024
#define STOPK 2048
#define FORCE_V 30
#define FORCE_S 100
#define SCALE 0.08838834764831845f
#define NW (SEQ / 32)   // 128 mask words per head
#define QS_STRIDE 132   // padded Q row stride (floats)

// ---------------- device scratch ----------------
__device__ float    g_probs[NH * LQ * SEQ];      // unnormalized exp scores, 8 MB
__device__ float    g_vert [NH * SEQ];
__device__ float    g_slash[NH * SEQ];
__device__ unsigned g_vbits[NH * NW];
__device__ unsigned g_sbits[NH * NW];

// ---------------- cp.async helpers ----------------
__device__ __forceinline__ void cpa16(float* dst, const float* src) {
    unsigned d = (unsigned)__cvta_generic_to_shared(dst);
    asm volatile("cp.async.cg.shared.global [%0], [%1], 16;\n" :: "r"(d), "l"(src));
}
__device__ __forceinline__ void cpa_commit() { asm volatile("cp.async.commit_group;\n" ::); }
__device__ __forceinline__ void cpa_wait0()  { asm volatile("cp.async.wait_group 0;\n" ::); }

// ---------------- kernel A: exp-scores for last 64 queries (tiled GEMM) ----------------
__global__ void pattern_kernel(const float* __restrict__ q,
                               const float* __restrict__ k) {
    extern __shared__ float psm[];
    float* Qs = psm;                 // [64][132] padded, pre-scaled
    float* Ks = Qs + 64 * QS_STRIDE; // [128][128] swizzled
    int h  = blockIdx.y;
    int j0 = blockIdx.x * 128;
    int tid = threadIdx.x;           // 256
    int ty = tid >> 4, tx = tid & 15;

    for (int e = tid; e < 64 * 32; e += 256) {
        int r = e >> 5, c = e & 31;
        float4 t = *(const float4*)&q[((size_t)(h * SEQ + SEQ - LQ + r)) * DH + (c << 2)];
        t.x *= SCALE; t.y *= SCALE; t.z *= SCALE; t.w *= SCALE;
        *(float4*)&Qs[r * QS_STRIDE + (c << 2)] = t;
    }
    for (int e = tid; e < 128 * 32; e += 256) {
        int r = e >> 5, c = e & 31;
        *(float4*)&Ks[r * 128 + ((c ^ (r >> 2)) << 2)] =
            *(const float4*)&k[((size_t)(h * SEQ + j0 + r)) * DH + (c << 2)];
    }
    __syncthreads();

    float s[4][8];
    #pragma unroll
    for (int a = 0; a < 4; a++)
        #pragma unroll
        for (int b = 0; b < 8; b++) s[a][b] = 0.f;

    #pragma unroll 4
    for (int c = 0; c < 32; c++) {
        float4 qv[4], kv[8];
        #pragma unroll
        for (int a = 0; a < 4; a++)
            qv[a] = *(const float4*)&Qs[(ty * 4 + a) * QS_STRIDE + (c << 2)];
        #pragma unroll
        for (int b = 0; b < 8; b++) {
            int r = tx * 8 + b;
            kv[b] = *(const float4*)&Ks[r * 128 + ((c ^ (r >> 2)) << 2)];
        }
        #pragma unroll
        for (int a = 0; a < 4; a++)
            #pragma unroll
            for (int b = 0; b < 8; b++)
                s[a][b] += qv[a].x * kv[b].x + qv[a].y * kv[b].y
                         + qv[a].z * kv[b].z + qv[a].w * kv[b].w;
    }

    #pragma unroll
    for (int a = 0; a < 4; a++) {
        int row  = ty * 4 + a;
        int qpos = SEQ - LQ + row;
        float p[8];
        #pragma unroll
        for (int b = 0; b < 8; b++) {
            int j = j0 + tx * 8 + b;
            p[b] = (j <= qpos) ? __expf(s[a][b]) : 0.f;
        }
        float* dst = &g_probs[((size_t)(h * LQ + row)) * SEQ + j0 + tx * 8];
        *(float4*)&dst[0] = make_float4(p[0], p[1], p[2], p[3]);
        *(float4*)&dst[4] = make_float4(p[4], p[5], p[6], p[7]);
    }
}

// ---------------- kernel B: rowsums (deterministic) + vertical + slash ----------------
__global__ void reduce_kernel() {
    int h = blockIdx.x;
    int tid = threadIdx.x;  // 256
    __shared__ float part[256];
    __shared__ float inv[LQ];
    const float* pb = &g_probs[(size_t)h * LQ * SEQ];

    // deterministic row sums: 4 threads per row, fixed order
    {
        int r = tid >> 2, qd = tid & 3;
        const float* rowp = &pb[(size_t)r * SEQ];
        float sm = 0.f;
        for (int j = qd; j < SEQ; j += 4) sm += rowp[j];
        part[tid] = sm;
    }
    __syncthreads();
    if (tid < LQ)
        inv[tid] = 1.0f / (part[tid * 4] + part[tid * 4 + 1] +
                           part[tid * 4 + 2] + part[tid * 4 + 3]);
    __syncthreads();

    for (int j = tid; j < SEQ; j += 256) {
        float s = 0.f;
        #pragma unroll 8
        for (int lq = 0; lq < LQ; lq++) s += pb[(size_t)lq * SEQ + j] * inv[lq];
        g_vert[h * SEQ + j] = (j < FORCE_V) ? INFINITY : s;
    }
    for (int d = tid; d < SEQ; d += 256) {
        float s = 0.f;
        #pragma unroll 8
        for (int lq = 0; lq < LQ; lq++) {
            int idx = (SEQ - LQ) + lq - d;
            if (idx >= 0) s += pb[(size_t)lq * SEQ + idx] * inv[lq];
        }
        g_slash[h * SEQ + d] = (d < FORCE_S) ? INFINITY : s;
    }
}

// ---------------- kernel C: exact top-k -> bitmask (jax tie-break) ----------------
__global__ void topk_kernel() {
    int which = blockIdx.x;   // 0 = vertical, 1 = slash
    int h     = blockIdx.y;
    const float* arr = which ? &g_slash[h * SEQ] : &g_vert[h * SEQ];
    unsigned*   bits = which ? &g_sbits[h * NW]  : &g_vbits[h * NW];
    const int K = which ? STOPK : VTOPK;

    __shared__ unsigned long long keys[SEQ];  // 32 KB
    int tid = threadIdx.x;  // 1024

    if (tid < NW) bits[tid] = 0u;
    for (int i = tid; i < SEQ; i += 1024) {
        unsigned vb = __float_as_uint(arr[i]);   // values >= 0 -> monotonic bits
        keys[i] = ((unsigned long long)vb << 32) | (unsigned)(SEQ - 1 - i);
    }
    __syncthreads();

    for (int kk = 2; kk <= SEQ; kk <<= 1) {
        for (int j = kk >> 1; j > 0; j >>= 1) {
            for (int i = tid; i < SEQ; i += 1024) {
                int ixj = i ^ j;
                if (ixj > i) {
                    unsigned long long a = keys[i], b = keys[ixj];
                    bool up = ((i & kk) == 0);
                    if ((a > b) == up) { keys[i] = b; keys[ixj] = a; }
                }
            }
            __syncthreads();
        }
    }
    for (int t = tid; t < K; t += 1024) {
        int idx = (SEQ - 1) - (int)(keys[SEQ - 1 - t] & 0xffffffffu);
        atomicOr(&bits[idx >> 5], 1u << (idx & 31));
    }
}

// ---------------- kernel D: masked causal flash attention ----------------
// smem: Qs[64*132] + 4 KV buffers[8192 each] + Ps[4096] + masks
#define FL_SMEM_FLOATS (64 * QS_STRIDE + 4 * 8192 + 4096)
#define FL_SMEM_BYTES  (FL_SMEM_FLOATS * 4 + 2 * NW * 4)

__global__ void __launch_bounds__(256, 1)
flash_kernel(const float* __restrict__ q, const float* __restrict__ k,
             const float* __restrict__ v, float* __restrict__ out) {
    extern __shared__ float smem[];
    float* Qs = smem;                        // [64][132] padded, pre-scaled
    float* KV = Qs + 64 * QS_STRIDE;         // 4 buffers: K0 V0 K1 V1
    float* Ps = KV + 4 * 8192;               // [64][64]
    unsigned* vb = (unsigned*)(Ps + 64 * 64);
    unsigned* sb = vb + NW;

    int bid = blockIdx.x;
    int h  = bid & 7;
    int it = 63 - (bid >> 3);       // heavy tiles first
    int tid = threadIdx.x;
    int ty = tid >> 4, tx = tid & 15;

    if (tid < NW)            vb[tid]      = g_vbits[h * NW + tid];
    else if (tid < 2 * NW)   sb[tid - NW] = g_sbits[h * NW + tid - NW];

    const size_t base = (size_t)h * SEQ * DH;
    const int i0 = it * 64;

    // Q tile: unswizzled padded (reads are broadcast), pre-scaled
    for (int e = tid; e < 2048; e += 256) {
        int r = e >> 5, c = e & 31;
        float4 t = *(const float4*)&q[base + (size_t)(i0 + r) * DH + (c << 2)];
        t.x *= SCALE; t.y *= SCALE; t.z *= SCALE; t.w *= SCALE;
        *(float4*)&Qs[r * QS_STRIDE + (c << 2)] = t;
    }

    // preload jt=0 K/V via cp.async
    {
        float* Kb = KV; float* Vb = KV + 8192;
        for (int e = tid; e < 2048; e += 256) {
            int r = e >> 5, c = e & 31;
            int sw = r * 128 + ((c ^ (r >> 2)) << 2);
            size_t g = base + (size_t)r * DH + (c << 2);
            cpa16(&Kb[sw], &k[g]);
            cpa16(&Vb[sw], &v[g]);
        }
        cpa_commit();
    }

    float o[4][8];
    float l_i[4];
    #pragma unroll
    for (int a = 0; a < 4; a++) {
        l_i[a] = 0.f;
        #pragma unroll
        for (int cc = 0; cc < 8; cc++) o[a][cc] = 0.f;
    }

    for (int jt = 0; jt <= it; jt++) {
        cpa_wait0();
        __syncthreads();
        float* Kc = KV + (jt & 1) * 16384;
        float* Vc = Kc + 8192;

        // prefetch next tile
        if (jt < it) {
            float* Kn = KV + ((jt + 1) & 1) * 16384;
            float* Vn = Kn + 8192;
            size_t gb = base + (size_t)(jt + 1) * 64 * DH;
            for (int e = tid; e < 2048; e += 256) {
                int r = e >> 5, c = e & 31;
                int sw = r * 128 + ((c ^ (r >> 2)) << 2);
                size_t g = gb + (size_t)r * DH + (c << 2);
                cpa16(&Kn[sw], &k[g]);
                cpa16(&Vn[sw], &v[g]);
            }
            cpa_commit();
        }

        // ---- QK^T ----
        float s[4][4];
        #pragma unroll
        for (int a = 0; a < 4; a++)
            #pragma unroll
            for (int b = 0; b < 4; b++) s[a][b] = 0.f;

        const float* Qb  = Qs + (ty * 4) * QS_STRIDE;
        const float* Kb4 = Kc + (tx * 4) * 128;
        #pragma unroll 8
        for (int c = 0; c < 32; c++) {
            int kx = ((c ^ tx) << 2);
            float4 qv[4], kv[4];
            #pragma unroll
            for (int a = 0; a < 4; a++) qv[a] = *(const float4*)&Qb[a * QS_STRIDE + (c << 2)];
            #pragma unroll
            for (int b = 0; b < 4; b++) kv[b] = *(const float4*)&Kb4[b * 128 + kx];
            #pragma unroll
            for (int a = 0; a < 4; a++)
                #pragma unroll
                for (int b = 0; b < 4; b++)
                    s[a][b] += qv[a].x * kv[b].x + qv[a].y * kv[b].y
                             + qv[a].z * kv[b].z + qv[a].w * kv[b].w;
        }

        // ---- mask + exp (max-free), store P ----
        int j_g0 = jt * 64 + tx * 4;
        unsigned vnib = (vb[j_g0 >> 5] >> (j_g0 & 31)) & 0xFu;
        int D0 = i0 + ty * 4 - j_g0;     // d for (a=0,b=0)
        // slash bits for d = D0-3 .. D0+3 (7 values cover all (a,b))
        unsigned smask = 0;
        #pragma unroll
        for (int t = 0; t < 7; t++) {
            int dd = D0 - 3 + t;
            unsigned bit = (dd >= 0) ? ((sb[dd >> 5] >> (dd & 31)) & 1u) : 0u;
            smask |= bit << t;
        }
        #pragma unroll
        for (int a = 0; a < 4; a++) {
            float p[4]; float rs = 0.f;
            #pragma unroll
            for (int b = 0; b < 4; b++) {
                int d = D0 + a - b;
                bool ok = (d >= 0) &&
                          (((vnib >> b) & 1u) || ((smask >> (a - b + 3)) & 1u));
                float pe = ok ? __expf(s[a][b]) : 0.f;
                p[b] = pe; rs += pe;
            }
            l_i[a] += rs;
            *(float4*)&Ps[(ty * 4 + a) * 64 + ((tx ^ ty) << 2)] =
                make_float4(p[0], p[1], p[2], p[3]);
        }
        __syncthreads();

        // ---- P @ V ----
        #pragma unroll 4
        for (int kc = 0; kc < 16; kc++) {
            float4 pv[4];
            #pragma unroll
            for (int a = 0; a < 4; a++)
                pv[a] = *(const float4*)&Ps[(ty * 4 + a) * 64 + ((kc ^ ty) << 2)];
            #pragma unroll
            for (int u = 0; u < 4; u++) {
                int kk = kc * 4 + u;
                const float4 v0 = *(const float4*)&Vc[kk * 128 + (((2 * tx)     ^ (kk >> 2)) << 2)];
                const float4 v1 = *(const float4*)&Vc[kk * 128 + (((2 * tx + 1) ^ (kk >> 2)) << 2)];
                #pragma unroll
                for (int a = 0; a < 4; a++) {
                    float p = ((const float*)&pv[a])[u];
                    o[a][0] += p * v0.x; o[a][1] += p * v0.y;
                    o[a][2] += p * v0.z; o[a][3] += p * v0.w;
                    o[a][4] += p * v1.x; o[a][5] += p * v1.y;
                    o[a][6] += p * v1.z; o[a][7] += p * v1.w;
                }
            }
        }
    }

    // ---- epilogue: reduce l across the 16 lanes of each row, normalize, store ----
    #pragma unroll
    for (int a = 0; a < 4; a++) {
        float l = l_i[a];
        #pragma unroll
        for (int m = 1; m < 16; m <<= 1) l += __shfl_xor_sync(0xffffffffu, l, m);
        float inv = 1.0f / l;
        int i_g = i0 + ty * 4 + a;
        float4 r0 = make_float4(o[a][0] * inv, o[a][1] * inv, o[a][2] * inv, o[a][3] * inv);
        float4 r1 = make_float4(o[a][4] * inv, o[a][5] * inv, o[a][6] * inv, o[a][7] * inv);
        *(float4*)&out[base + (size_t)i_g * DH + tx * 8]     = r0;
        *(float4*)&out[base + (size_t)i_g * DH + tx * 8 + 4] = r1;
    }
}

// ---------------- launch ----------------
extern "C" void kernel_launch(void* const* d_in, const int* in_sizes, int n_in,
                              void* d_out, int out_size) {
    const float* q = (const float*)d_in[0];
    const float* k = (const float*)d_in[1];
    const float* v = (const float*)d_in[2];
    float* out = (float*)d_out;

    int psm = (64 * QS_STRIDE + 128 * 128) * 4;
    cudaFuncSetAttribute(pattern_kernel,
                         cudaFuncAttributeMaxDynamicSharedMemorySize, psm);
    pattern_kernel<<<dim3(SEQ / 128, NH), 256, psm>>>(q, k);
    reduce_kernel<<<NH, 256>>>();
    topk_kernel<<<dim3(2, NH), 1024>>>();

    cudaFuncSetAttribute(flash_kernel,
                         cudaFuncAttributeMaxDynamicSharedMemorySize, FL_SMEM_BYTES);
    flash_kernel<<<64 * NH, 256, FL_SMEM_BYTES>>>(q, k, v, out);
}

// round 4
// speedup vs baseline: 2.2013x; 2.2013x over previous
#include <cuda_runtime.h>
#include <cuda_bf16.h>
#include <math.h>
#include <float.h>

#define NH 8
#define SEQ 4096
#define DH 128
#define LQ 64
#define VTOPK 1024
#define STOPK 2048
#define FORCE_V 30
#define FORCE_S 100
#define SCALE 0.08838834764831845f
#define NW (SEQ / 32)
#define QS_STRIDE 132
#define NPAIR (NH * SEQ * DH / 2)

// ---------------- device scratch ----------------
__device__ float    g_probs[NH * LQ * SEQ];
__device__ float    g_vert [NH * SEQ];
__device__ float    g_slash[NH * SEQ];
__device__ unsigned g_vbits[NH * NW];
__device__ unsigned g_sbits[NH * NW];
// bf16 hi/lo splits, 2 elems packed per u32 (low = even index)
__device__ unsigned g_qh[NPAIR], g_ql[NPAIR];
__device__ unsigned g_kh[NPAIR], g_kl[NPAIR];
__device__ unsigned g_vh[NPAIR], g_vl[NPAIR];

// ---------------- helpers ----------------
__device__ __forceinline__ void cpa16(unsigned dst, const void* src) {
    asm volatile("cp.async.cg.shared.global [%0], [%1], 16;\n" :: "r"(dst), "l"(src));
}
__device__ __forceinline__ void cpa_commit() { asm volatile("cp.async.commit_group;\n" ::); }
__device__ __forceinline__ void cpa_wait0()  { asm volatile("cp.async.wait_group 0;\n" ::); }

__device__ __forceinline__ void ldsm4(unsigned* r, unsigned a) {
    asm volatile("ldmatrix.sync.aligned.m8n8.x4.shared.b16 {%0,%1,%2,%3}, [%4];"
        : "=r"(r[0]), "=r"(r[1]), "=r"(r[2]), "=r"(r[3]) : "r"(a));
}
__device__ __forceinline__ void ldsm4t(unsigned* r, unsigned a) {
    asm volatile("ldmatrix.sync.aligned.m8n8.x4.trans.shared.b16 {%0,%1,%2,%3}, [%4];"
        : "=r"(r[0]), "=r"(r[1]), "=r"(r[2]), "=r"(r[3]) : "r"(a));
}
__device__ __forceinline__ void mma16(float* d, const unsigned* a, unsigned b0, unsigned b1) {
    asm volatile("mma.sync.aligned.m16n8k16.row.col.f32.bf16.bf16.f32 "
        "{%0,%1,%2,%3}, {%4,%5,%6,%7}, {%8,%9}, {%0,%1,%2,%3};"
        : "+f"(d[0]), "+f"(d[1]), "+f"(d[2]), "+f"(d[3])
        : "r"(a[0]), "r"(a[1]), "r"(a[2]), "r"(a[3]), "r"(b0), "r"(b1));
}
__device__ __forceinline__ unsigned pk2(float x, float y) {
    __nv_bfloat162 t = __floats2bfloat162_rn(x, y);
    return *(unsigned*)&t;
}

// ---------------- prep: split q*scale, k, v into bf16 hi/lo ----------------
__global__ void prep_kernel(const float* __restrict__ q, const float* __restrict__ k,
                            const float* __restrict__ v) {
    int i = blockIdx.x * 256 + threadIdx.x;
    if (i >= NPAIR) return;
    float2 a = ((const float2*)q)[i];
    a.x *= SCALE; a.y *= SCALE;
    float hx = __bfloat162float(__float2bfloat16_rn(a.x));
    float hy = __bfloat162float(__float2bfloat16_rn(a.y));
    g_qh[i] = pk2(hx, hy); g_ql[i] = pk2(a.x - hx, a.y - hy);
    a = ((const float2*)k)[i];
    hx = __bfloat162float(__float2bfloat16_rn(a.x));
    hy = __bfloat162float(__float2bfloat16_rn(a.y));
    g_kh[i] = pk2(hx, hy); g_kl[i] = pk2(a.x - hx, a.y - hy);
    a = ((const float2*)v)[i];
    hx = __bfloat162float(__float2bfloat16_rn(a.x));
    hy = __bfloat162float(__float2bfloat16_rn(a.y));
    g_vh[i] = pk2(hx, hy); g_vl[i] = pk2(a.x - hx, a.y - hy);
}

// ---------------- kernel A: exp-scores for last 64 queries ----------------
__global__ void pattern_kernel(const float* __restrict__ q, const float* __restrict__ k) {
    extern __shared__ float psm[];
    float* Qs = psm;
    float* Ks = Qs + 64 * QS_STRIDE;
    int h = blockIdx.y, j0 = blockIdx.x * 128;
    int tid = threadIdx.x, ty = tid >> 4, tx = tid & 15;

    for (int e = tid; e < 64 * 32; e += 256) {
        int r = e >> 5, c = e & 31;
        float4 t = *(const float4*)&q[((size_t)(h * SEQ + SEQ - LQ + r)) * DH + (c << 2)];
        t.x *= SCALE; t.y *= SCALE; t.z *= SCALE; t.w *= SCALE;
        *(float4*)&Qs[r * QS_STRIDE + (c << 2)] = t;
    }
    for (int e = tid; e < 128 * 32; e += 256) {
        int r = e >> 5, c = e & 31;
        *(float4*)&Ks[r * 128 + ((c ^ (r >> 2)) << 2)] =
            *(const float4*)&k[((size_t)(h * SEQ + j0 + r)) * DH + (c << 2)];
    }
    __syncthreads();

    float s[4][8];
    #pragma unroll
    for (int a = 0; a < 4; a++)
        #pragma unroll
        for (int b = 0; b < 8; b++) s[a][b] = 0.f;

    #pragma unroll 4
    for (int c = 0; c < 32; c++) {
        float4 qv[4], kv[8];
        #pragma unroll
        for (int a = 0; a < 4; a++)
            qv[a] = *(const float4*)&Qs[(ty * 4 + a) * QS_STRIDE + (c << 2)];
        #pragma unroll
        for (int b = 0; b < 8; b++) {
            int r = tx * 8 + b;
            kv[b] = *(const float4*)&Ks[r * 128 + ((c ^ (r >> 2)) << 2)];
        }
        #pragma unroll
        for (int a = 0; a < 4; a++)
            #pragma unroll
            for (int b = 0; b < 8; b++)
                s[a][b] += qv[a].x * kv[b].x + qv[a].y * kv[b].y
                         + qv[a].z * kv[b].z + qv[a].w * kv[b].w;
    }
    #pragma unroll
    for (int a = 0; a < 4; a++) {
        int row = ty * 4 + a, qpos = SEQ - LQ + row;
        float p[8];
        #pragma unroll
        for (int b = 0; b < 8; b++) {
            int j = j0 + tx * 8 + b;
            p[b] = (j <= qpos) ? __expf(s[a][b]) : 0.f;
        }
        float* dst = &g_probs[((size_t)(h * LQ + row)) * SEQ + j0 + tx * 8];
        *(float4*)&dst[0] = make_float4(p[0], p[1], p[2], p[3]);
        *(float4*)&dst[4] = make_float4(p[4], p[5], p[6], p[7]);
    }
}

// ---------------- kernel B ----------------
__global__ void reduce_kernel() {
    int h = blockIdx.x, tid = threadIdx.x;
    __shared__ float part[256];
    __shared__ float inv[LQ];
    const float* pb = &g_probs[(size_t)h * LQ * SEQ];
    {
        int r = tid >> 2, qd = tid & 3;
        const float* rowp = &pb[(size_t)r * SEQ];
        float sm = 0.f;
        for (int j = qd; j < SEQ; j += 4) sm += rowp[j];
        part[tid] = sm;
    }
    __syncthreads();
    if (tid < LQ)
        inv[tid] = 1.0f / (part[tid*4] + part[tid*4+1] + part[tid*4+2] + part[tid*4+3]);
    __syncthreads();
    for (int j = tid; j < SEQ; j += 256) {
        float s = 0.f;
        #pragma unroll 8
        for (int lq = 0; lq < LQ; lq++) s += pb[(size_t)lq * SEQ + j] * inv[lq];
        g_vert[h * SEQ + j] = (j < FORCE_V) ? INFINITY : s;
    }
    for (int d = tid; d < SEQ; d += 256) {
        float s = 0.f;
        #pragma unroll 8
        for (int lq = 0; lq < LQ; lq++) {
            int idx = (SEQ - LQ) + lq - d;
            if (idx >= 0) s += pb[(size_t)lq * SEQ + idx] * inv[lq];
        }
        g_slash[h * SEQ + d] = (d < FORCE_S) ? INFINITY : s;
    }
}

// ---------------- kernel C: exact top-k -> bitmask ----------------
__global__ void topk_kernel() {
    int which = blockIdx.x, h = blockIdx.y;
    const float* arr = which ? &g_slash[h * SEQ] : &g_vert[h * SEQ];
    unsigned*   bits = which ? &g_sbits[h * NW]  : &g_vbits[h * NW];
    const int K = which ? STOPK : VTOPK;
    __shared__ unsigned long long keys[SEQ];
    int tid = threadIdx.x;
    if (tid < NW) bits[tid] = 0u;
    for (int i = tid; i < SEQ; i += 1024) {
        unsigned vb = __float_as_uint(arr[i]);
        keys[i] = ((unsigned long long)vb << 32) | (unsigned)(SEQ - 1 - i);
    }
    __syncthreads();
    for (int kk = 2; kk <= SEQ; kk <<= 1)
        for (int j = kk >> 1; j > 0; j >>= 1) {
            for (int i = tid; i < SEQ; i += 1024) {
                int ixj = i ^ j;
                if (ixj > i) {
                    unsigned long long a = keys[i], b = keys[ixj];
                    bool up = ((i & kk) == 0);
                    if ((a > b) == up) { keys[i] = b; keys[ixj] = a; }
                }
            }
            __syncthreads();
        }
    for (int t = tid; t < K; t += 1024) {
        int idx = (SEQ - 1) - (int)(keys[SEQ - 1 - t] & 0xffffffffu);
        atomicOr(&bits[idx >> 5], 1u << (idx & 31));
    }
}

// ---------------- kernel D: tensor-core masked flash attention ----------------
// smem bytes: QH 0..16K, QL 16K..32K, vb@32768(512B), sb@33280(512B),
// stage0@34816 (Kh,Kl,Vh,Vl 16K each = 64K), stage1@100352. total 165888.
#define SM_QH 0
#define SM_QL 16384
#define SM_VB 32768
#define SM_SB 33280
#define SM_ST 34816
#define SM_STSZ 65536
#define FL_BYTES 165888

__global__ void __launch_bounds__(256, 1)
flash_mma_kernel(float* __restrict__ out) {
    extern __shared__ unsigned char smem[];
    const unsigned sb0 = (unsigned)__cvta_generic_to_shared(smem);
    unsigned* vbm = (unsigned*)(smem + SM_VB);
    unsigned* sbm = (unsigned*)(smem + SM_SB);

    int bid = blockIdx.x;
    int h   = bid & 7;
    int it  = 63 - (bid >> 3);
    int tid = threadIdx.x, lane = tid & 31, w = tid >> 5;
    int qw = w & 3, kh = w >> 2;        // row-group, key-half
    int g = lane >> 2, t = lane & 3;
    const int i0 = it * 64, qr0 = qw * 16;
    const size_t hb = (size_t)h * SEQ * 64;   // u32-pair base

    if (tid < NW)            vbm[tid]      = g_vbits[h * NW + tid];
    else if (tid < 2 * NW)   sbm[tid - NW] = g_sbits[h * NW + tid - NW];

    // Q tiles (rows i0..i0+63): 64 rows x 16 chunks x 2 arrays
    for (int i = 0; i < 4; i++) {
        int e = tid + i * 256;           // 0..1023
        int r = e >> 4, c = e & 15;
        unsigned off = (unsigned)(r * 256 + ((c ^ (r & 7)) << 4));
        const unsigned* src = &g_qh[hb + (size_t)(i0 + r) * 64 + c * 4];
        cpa16(sb0 + SM_QH + off, src);
        cpa16(sb0 + SM_QL + off, src + (g_ql - g_qh));
    }
    // stage 0 K/V
    {
        unsigned st = sb0 + SM_ST;
        for (int i = 0; i < 4; i++) {
            int e = tid + i * 256;
            int r = e >> 4, c = e & 15;
            unsigned off = (unsigned)(r * 256 + ((c ^ (r & 7)) << 4));
            size_t gi = hb + (size_t)r * 64 + c * 4;
            cpa16(st + off,          &g_kh[gi]);
            cpa16(st + 16384 + off,  &g_kl[gi]);
            cpa16(st + 32768 + off,  &g_vh[gi]);
            cpa16(st + 49152 + off,  &g_vl[gi]);
        }
        cpa_commit();
    }

    float O[16][4];
    #pragma unroll
    for (int o = 0; o < 16; o++) { O[o][0]=0;O[o][1]=0;O[o][2]=0;O[o][3]=0; }
    float lg = 0.f, lg8 = 0.f;
    const int iA = i0 + qr0 + g;

    for (int jt = 0; jt <= it; jt++) {
        cpa_wait0();
        __syncthreads();
        unsigned st = sb0 + SM_ST + (jt & 1) * SM_STSZ;
        if (jt < it) {
            unsigned sn = sb0 + SM_ST + ((jt + 1) & 1) * SM_STSZ;
            size_t gb = hb + (size_t)(jt + 1) * 64 * 64;
            for (int i = 0; i < 4; i++) {
                int e = tid + i * 256;
                int r = e >> 4, c = e & 15;
                unsigned off = (unsigned)(r * 256 + ((c ^ (r & 7)) << 4));
                size_t gi = gb + (size_t)r * 64 + c * 4;
                cpa16(sn + off,         &g_kh[gi]);
                cpa16(sn + 16384 + off, &g_kl[gi]);
                cpa16(sn + 32768 + off, &g_vh[gi]);
                cpa16(sn + 49152 + off, &g_vl[gi]);
            }
            cpa_commit();
        }

        // ---- QK: S[16 rows][32 keys] per warp, 4 n-tiles ----
        float S[4][4];
        #pragma unroll
        for (int n = 0; n < 4; n++) { S[n][0]=0;S[n][1]=0;S[n][2]=0;S[n][3]=0; }

        int am = (lane >> 3) & 1, ar = lane & 7, ac = lane >> 4;
        #pragma unroll
        for (int ks = 0; ks < 8; ks++) {
            unsigned ah[4], al[4];
            {
                int row = qr0 + am * 8 + ar, ch = ks * 2 + ac;
                unsigned a = sb0 + SM_QH + row * 256 + ((ch ^ (row & 7)) << 4);
                ldsm4(ah, a); ldsm4(al, a + 16384);
            }
            #pragma unroll
            for (int kt = 0; kt < 2; kt++) {
                unsigned bh[4], bl[4];
                int row = kh * 32 + kt * 16 + am * 8 + ar, ch = ks * 2 + ac;
                unsigned a = st + row * 256 + ((ch ^ (row & 7)) << 4);
                ldsm4(bh, a); ldsm4(bl, a + 16384);
                mma16(S[kt*2],   ah, bh[0], bh[2]);
                mma16(S[kt*2],   ah, bl[0], bl[2]);
                mma16(S[kt*2],   al, bh[0], bh[2]);
                mma16(S[kt*2+1], ah, bh[1], bh[3]);
                mma16(S[kt*2+1], ah, bl[1], bl[3]);
                mma16(S[kt*2+1], al, bh[1], bh[3]);
            }
        }

        // ---- mask + exp ----
        int jb = jt * 64 + kh * 32;
        unsigned vw = vbm[jb >> 5];
        #pragma unroll
        for (int n = 0; n < 4; n++) {
            int cb = n * 8 + 2 * t;       // col bit base within 32
            #pragma unroll
            for (int e = 0; e < 4; e++) {
                int roff = (e >> 1) * 8, b = e & 1;
                int j = jb + cb + b;
                int d = iA + roff - j;
                unsigned sbit = (d >= 0) ? ((sbm[d >> 5] >> (d & 31)) & 1u) : 0u;
                bool ok = (d >= 0) && (((vw >> (cb + b)) & 1u) || sbit);
                float p = ok ? __expf(S[n][e]) : 0.f;
                S[n][e] = p;
                if (e < 2) lg += p; else lg8 += p;
            }
        }

        // ---- PV ----
        #pragma unroll
        for (int kp = 0; kp < 2; kp++) {
            unsigned aph[4], apl[4];
            #pragma unroll
            for (int u = 0; u < 4; u++) {
                float x = S[kp*2 + (u>>1)][(u&1)*2], y = S[kp*2 + (u>>1)][(u&1)*2+1];
                // u: 0->(st even, c0c1) 1->(even, c2c3) 2->(odd, c0c1) 3->(odd, c2c3)
                float hx = __bfloat162float(__float2bfloat16_rn(x));
                float hy = __bfloat162float(__float2bfloat16_rn(y));
                int ai = (u == 1) ? 1 : (u == 2) ? 2 : (u == 3) ? 3 : 0;
                aph[ai] = pk2(hx, hy);
                apl[ai] = pk2(x - hx, y - hy);
            }
            // fix mapping: a0=(even c0c1) a1=(even c2c3) a2=(odd c0c1) a3=(odd c2c3)
            // u loop above: u0->a0(even c0c1), u1->a1(even c2c3), u2->a2, u3->a3  (ai==u)
            #pragma unroll
            for (int n2 = 0; n2 < 8; n2++) {
                unsigned vh4[4], vl4[4];
                int row = kh * 32 + kp * 16 + am * 8 + ar, ch = n2 * 2 + ac;
                unsigned a = st + 32768 + row * 256 + ((ch ^ (row & 7)) << 4);
                ldsm4t(vh4, a); ldsm4t(vl4, a + 16384);
                mma16(O[n2*2],   aph, vh4[0], vh4[1]);
                mma16(O[n2*2],   aph, vl4[0], vl4[1]);
                mma16(O[n2*2],   apl, vh4[0], vh4[1]);
                mma16(O[n2*2+1], aph, vh4[2], vh4[3]);
                mma16(O[n2*2+1], aph, vl4[2], vl4[3]);
                mma16(O[n2*2+1], apl, vh4[2], vh4[3]);
            }
        }
    }

    // ---- epilogue: reduce across key-halves via smem ----
    __syncthreads();
    float* Op = (float*)(smem + SM_ST);              // [64][128]
    float* lp = (float*)(smem + SM_ST + 32768);      // [64]
    lg  += __shfl_xor_sync(0xffffffffu, lg, 1);  lg  += __shfl_xor_sync(0xffffffffu, lg, 2);
    lg8 += __shfl_xor_sync(0xffffffffu, lg8, 1); lg8 += __shfl_xor_sync(0xffffffffu, lg8, 2);
    if (kh == 1) {
        #pragma unroll
        for (int o = 0; o < 16; o++) {
            *(float2*)&Op[(qr0+g)*128   + o*8 + 2*t] = make_float2(O[o][0], O[o][1]);
            *(float2*)&Op[(qr0+g+8)*128 + o*8 + 2*t] = make_float2(O[o][2], O[o][3]);
        }
        if (t == 0) { lp[qr0+g] = lg; lp[qr0+g+8] = lg8; }
    }
    __syncthreads();
    if (kh == 0) {
        float inv0 = 1.0f / (lg  + lp[qr0+g]);
        float inv1 = 1.0f / (lg8 + lp[qr0+g+8]);
        size_t ob = (size_t)h * SEQ * DH;
        #pragma unroll
        for (int o = 0; o < 16; o++) {
            float2 p0 = *(float2*)&Op[(qr0+g)*128   + o*8 + 2*t];
            float2 p1 = *(float2*)&Op[(qr0+g+8)*128 + o*8 + 2*t];
            *(float2*)&out[ob + (size_t)(i0+qr0+g)*DH   + o*8 + 2*t] =
                make_float2((O[o][0] + p0.x) * inv0, (O[o][1] + p0.y) * inv0);
            *(float2*)&out[ob + (size_t)(i0+qr0+g+8)*DH + o*8 + 2*t] =
                make_float2((O[o][2] + p1.x) * inv1, (O[o][3] + p1.y) * inv1);
        }
    }
}

// ---------------- launch ----------------
extern "C" void kernel_launch(void* const* d_in, const int* in_sizes, int n_in,
                              void* d_out, int out_size) {
    const float* q = (const float*)d_in[0];
    const float* k = (const float*)d_in[1];
    const float* v = (const float*)d_in[2];
    float* out = (float*)d_out;

    prep_kernel<<<(NPAIR + 255) / 256, 256>>>(q, k, v);

    int psm = (64 * QS_STRIDE + 128 * 128) * 4;
    cudaFuncSetAttribute(pattern_kernel, cudaFuncAttributeMaxDynamicSharedMemorySize, psm);
    pattern_kernel<<<dim3(SEQ / 128, NH), 256, psm>>>(q, k);
    reduce_kernel<<<NH, 256>>>();
    topk_kernel<<<dim3(2, NH), 1024>>>();

    cudaFuncSetAttribute(flash_mma_kernel, cudaFuncAttributeMaxDynamicSharedMemorySize, FL_BYTES);
    flash_mma_kernel<<<64 * NH, 256, FL_BYTES>>>(out);
}

// round 6
// speedup vs baseline: 2.6481x; 1.2030x over previous
#include <cuda_runtime.h>
#include <cuda_bf16.h>
#include <math.h>
#include <float.h>

#define NH 8
#define SEQ 4096
#define DH 128
#define LQ 64
#define VTOPK 1024
#define STOPK 2048
#define FORCE_V 30
#define FORCE_S 100
#define SCALE 0.08838834764831845f
#define NW (SEQ / 32)
#define QS_STRIDE 132
#define NPAIR (NH * SEQ * DH / 2)

// ---------------- device scratch ----------------
__device__ float    g_probs[NH * LQ * SEQ];
__device__ float    g_rowinv[NH * LQ];
__device__ float    g_vert [NH * SEQ];
__device__ float    g_slash[NH * SEQ];
__device__ unsigned g_vbits[NH * NW];
__device__ unsigned g_sbits[NH * NW];
__device__ unsigned g_qh[NPAIR], g_ql[NPAIR];
__device__ unsigned g_kh[NPAIR], g_kl[NPAIR];
__device__ unsigned g_vh[NPAIR], g_vl[NPAIR];

// ---------------- helpers ----------------
__device__ __forceinline__ void cpa16(unsigned dst, const void* src) {
    asm volatile("cp.async.cg.shared.global [%0], [%1], 16;\n" :: "r"(dst), "l"(src));
}
__device__ __forceinline__ void cpa_commit() { asm volatile("cp.async.commit_group;\n" ::); }
__device__ __forceinline__ void cpa_wait0()  { asm volatile("cp.async.wait_group 0;\n" ::); }

__device__ __forceinline__ void ldsm4(unsigned* r, unsigned a) {
    asm volatile("ldmatrix.sync.aligned.m8n8.x4.shared.b16 {%0,%1,%2,%3}, [%4];"
        : "=r"(r[0]), "=r"(r[1]), "=r"(r[2]), "=r"(r[3]) : "r"(a));
}
__device__ __forceinline__ void ldsm4t(unsigned* r, unsigned a) {
    asm volatile("ldmatrix.sync.aligned.m8n8.x4.trans.shared.b16 {%0,%1,%2,%3}, [%4];"
        : "=r"(r[0]), "=r"(r[1]), "=r"(r[2]), "=r"(r[3]) : "r"(a));
}
__device__ __forceinline__ void mma16(float* d, const unsigned* a, unsigned b0, unsigned b1) {
    asm volatile("mma.sync.aligned.m16n8k16.row.col.f32.bf16.bf16.f32 "
        "{%0,%1,%2,%3}, {%4,%5,%6,%7}, {%8,%9}, {%0,%1,%2,%3};"
        : "+f"(d[0]), "+f"(d[1]), "+f"(d[2]), "+f"(d[3])
        : "r"(a[0]), "r"(a[1]), "r"(a[2]), "r"(a[3]), "r"(b0), "r"(b1));
}
__device__ __forceinline__ unsigned pk2(float x, float y) {
    __nv_bfloat162 t = __floats2bfloat162_rn(x, y);
    return *(unsigned*)&t;
}

// ---------------- prep: split q*scale, k, v into bf16 hi/lo ----------------
__global__ void prep_kernel(const float* __restrict__ q, const float* __restrict__ k,
                            const float* __restrict__ v) {
    int i = blockIdx.x * 256 + threadIdx.x;
    if (i >= NPAIR) return;
    float2 a = ((const float2*)q)[i];
    a.x *= SCALE; a.y *= SCALE;
    float hx = __bfloat162float(__float2bfloat16_rn(a.x));
    float hy = __bfloat162float(__float2bfloat16_rn(a.y));
    g_qh[i] = pk2(hx, hy); g_ql[i] = pk2(a.x - hx, a.y - hy);
    a = ((const float2*)k)[i];
    hx = __bfloat162float(__float2bfloat16_rn(a.x));
    hy = __bfloat162float(__float2bfloat16_rn(a.y));
    g_kh[i] = pk2(hx, hy); g_kl[i] = pk2(a.x - hx, a.y - hy);
    a = ((const float2*)v)[i];
    hx = __bfloat162float(__float2bfloat16_rn(a.x));
    hy = __bfloat162float(__float2bfloat16_rn(a.y));
    g_vh[i] = pk2(hx, hy); g_vl[i] = pk2(a.x - hx, a.y - hy);
}

// ---------------- kernel A: exp-scores for last 64 queries ----------------
__global__ void pattern_kernel(const float* __restrict__ q, const float* __restrict__ k) {
    extern __shared__ float psm[];
    float* Qs = psm;
    float* Ks = Qs + 64 * QS_STRIDE;
    int h = blockIdx.y, j0 = blockIdx.x * 128;
    int tid = threadIdx.x, ty = tid >> 4, tx = tid & 15;

    for (int e = tid; e < 64 * 32; e += 256) {
        int r = e >> 5, c = e & 31;
        float4 t = *(const float4*)&q[((size_t)(h * SEQ + SEQ - LQ + r)) * DH + (c << 2)];
        t.x *= SCALE; t.y *= SCALE; t.z *= SCALE; t.w *= SCALE;
        *(float4*)&Qs[r * QS_STRIDE + (c << 2)] = t;
    }
    for (int e = tid; e < 128 * 32; e += 256) {
        int r = e >> 5, c = e & 31;
        *(float4*)&Ks[r * 128 + ((c ^ (r >> 2)) << 2)] =
            *(const float4*)&k[((size_t)(h * SEQ + j0 + r)) * DH + (c << 2)];
    }
    __syncthreads();

    float s[4][8];
    #pragma unroll
    for (int a = 0; a < 4; a++)
        #pragma unroll
        for (int b = 0; b < 8; b++) s[a][b] = 0.f;

    #pragma unroll 4
    for (int c = 0; c < 32; c++) {
        float4 qv[4], kv[8];
        #pragma unroll
        for (int a = 0; a < 4; a++)
            qv[a] = *(const float4*)&Qs[(ty * 4 + a) * QS_STRIDE + (c << 2)];
        #pragma unroll
        for (int b = 0; b < 8; b++) {
            int r = tx * 8 + b;
            kv[b] = *(const float4*)&Ks[r * 128 + ((c ^ (r >> 2)) << 2)];
        }
        #pragma unroll
        for (int a = 0; a < 4; a++)
            #pragma unroll
            for (int b = 0; b < 8; b++)
                s[a][b] += qv[a].x * kv[b].x + qv[a].y * kv[b].y
                         + qv[a].z * kv[b].z + qv[a].w * kv[b].w;
    }
    #pragma unroll
    for (int a = 0; a < 4; a++) {
        int row = ty * 4 + a, qpos = SEQ - LQ + row;
        float p[8];
        #pragma unroll
        for (int b = 0; b < 8; b++) {
            int j = j0 + tx * 8 + b;
            p[b] = (j <= qpos) ? __expf(s[a][b]) : 0.f;
        }
        float* dst = &g_probs[((size_t)(h * LQ + row)) * SEQ + j0 + tx * 8];
        *(float4*)&dst[0] = make_float4(p[0], p[1], p[2], p[3]);
        *(float4*)&dst[4] = make_float4(p[4], p[5], p[6], p[7]);
    }
}

// ---------------- kernel B1: deterministic row sums ----------------
__global__ void rowsum_kernel() {
    int b = blockIdx.x;
    int h = b >> 6, r = b & 63;
    const float* rowp = &g_probs[((size_t)(h * LQ + r)) * SEQ];
    int tid = threadIdx.x;              // 128
    float s = 0.f;
    for (int j = tid; j < SEQ; j += 128) s += rowp[j];
    __shared__ float red[128];
    red[tid] = s; __syncthreads();
    #pragma unroll
    for (int st = 64; st > 0; st >>= 1) {
        if (tid < st) red[tid] += red[tid + st];
        __syncthreads();
    }
    if (tid == 0) g_rowinv[h * LQ + r] = 1.0f / red[0];
}

// ---------------- kernel B2: vertical + slash (slice-parallel) ----------------
__global__ void reduce_kernel() {
    int h = blockIdx.x, seg = blockIdx.y;
    int tid = threadIdx.x;              // 256
    __shared__ float inv[LQ];
    if (tid < LQ) inv[tid] = g_rowinv[h * LQ + tid];
    __syncthreads();
    const float* pb = &g_probs[(size_t)h * LQ * SEQ];
    int j = seg * 256 + tid;
    float s = 0.f;
    #pragma unroll 8
    for (int lq = 0; lq < LQ; lq++) s += pb[(size_t)lq * SEQ + j] * inv[lq];
    g_vert[h * SEQ + j] = (j < FORCE_V) ? INFINITY : s;
    float t = 0.f;
    #pragma unroll 8
    for (int lq = 0; lq < LQ; lq++) {
        int idx = (SEQ - LQ) + lq - j;
        if (idx >= 0) t += pb[(size_t)lq * SEQ + idx] * inv[lq];
    }
    g_slash[h * SEQ + j] = (j < FORCE_S) ? INFINITY : t;
}

// ---------------- kernel C: exact top-k via radix select (jax tie-break) ----------------
__global__ void topk_kernel() {
    int which = blockIdx.x, h = blockIdx.y;
    const float* arr = which ? &g_slash[h * SEQ] : &g_vert[h * SEQ];
    unsigned*   bits = which ? &g_sbits[h * NW]  : &g_vbits[h * NW];
    const int K = which ? STOPK : VTOPK;

    __shared__ unsigned vals[SEQ];
    __shared__ unsigned hist[256];
    __shared__ unsigned s_prefix;
    __shared__ int s_rem;
    __shared__ unsigned gtw[NW], eqw[NW], wcnt[NW], psum[NW];
    int tid = threadIdx.x;              // 256

    for (int i = tid; i < SEQ; i += 256) vals[i] = __float_as_uint(arr[i]);
    __syncthreads();

    unsigned prefix = 0; int remaining = K;
    #pragma unroll
    for (int pass = 3; pass >= 0; pass--) {
        int shift = pass * 8;
        hist[tid] = 0u;
        __syncthreads();
        unsigned long long ph = (unsigned long long)prefix >> (shift + 8);
        for (int i = tid; i < SEQ; i += 256) {
            unsigned v = vals[i];
            if (((unsigned long long)v >> (shift + 8)) == ph)
                atomicAdd(&hist[(v >> shift) & 255u], 1u);
        }
        __syncthreads();
        if (tid == 0) {
            int cum = 0, b = 255;
            for (; b > 0; b--) {
                cum += (int)hist[b];
                if (cum >= remaining) break;
            }
            if (cum < remaining) cum += (int)hist[0];
            s_rem = remaining - (cum - (int)hist[b]);
            s_prefix = prefix | ((unsigned)b << shift);
        }
        __syncthreads();
        prefix = s_prefix; remaining = s_rem;
        __syncthreads();
    }

    if (tid < NW) {
        unsigned gm = 0, em = 0;
        #pragma unroll 8
        for (int b = 0; b < 32; b++) {
            unsigned v = vals[tid * 32 + b];
            gm |= (v > prefix ? 1u : 0u) << b;
            em |= (v == prefix ? 1u : 0u) << b;
        }
        gtw[tid] = gm; eqw[tid] = em; wcnt[tid] = __popc(em);
    }
    __syncthreads();
    if (tid == 0) {
        unsigned run = 0;
        for (int w = 0; w < NW; w++) { psum[w] = run; run += wcnt[w]; }
    }
    __syncthreads();
    if (tid < NW) {
        unsigned em = eqw[tid], sel = 0;
        int rank = (int)psum[tid];
        while (em) {
            int b = __ffs(em) - 1;
            if (rank < remaining) sel |= 1u << b;
            rank++;
            em &= em - 1;
        }
        bits[tid] = gtw[tid] | sel;
    }
}

// ---------------- kernel D: tensor-core masked flash attention ----------------
// smem: QH 0..16K, QL 16K..32K, vb@32768, sb@33280,
// stages @34816: each 64K = Kh Kl Vh Vl (16K each). total 165888.
#define SM_QH 0
#define SM_QL 16384
#define SM_VB 32768
#define SM_SB 33280
#define SM_ST 34816
#define SM_STSZ 65536
#define FL_BYTES (SM_ST + 2 * SM_STSZ)

__global__ void __launch_bounds__(256, 1)
flash_mma_kernel(float* __restrict__ out) {
    extern __shared__ unsigned char smem[];
    const unsigned sb0 = (unsigned)__cvta_generic_to_shared(smem);
    unsigned* vbm = (unsigned*)(smem + SM_VB);
    unsigned* sbm = (unsigned*)(smem + SM_SB);

    int bid = blockIdx.x;
    int h   = bid & 7;
    int it  = 63 - (bid >> 3);
    int tid = threadIdx.x, lane = tid & 31, w = tid >> 5;
    int qw = w & 3, kh = w >> 2;
    int g = lane >> 2, t = lane & 3;
    const int i0 = it * 64, qr0 = qw * 16;
    const size_t hb = (size_t)h * SEQ * 64;

    if (tid < NW)            vbm[tid]      = g_vbits[h * NW + tid];
    else if (tid < 2 * NW)   sbm[tid - NW] = g_sbits[h * NW + tid - NW];

    // Q tiles + stage 0, one commit group
    #pragma unroll
    for (int i = 0; i < 4; i++) {
        int e = tid + i * 256;
        int r = e >> 4, c = e & 15;
        unsigned off = (unsigned)(r * 256 + ((c ^ (r & 7)) << 4));
        size_t gq = hb + (size_t)(i0 + r) * 64 + c * 4;
        cpa16(sb0 + SM_QH + off, &g_qh[gq]);
        cpa16(sb0 + SM_QL + off, &g_ql[gq]);
        size_t gi = hb + (size_t)r * 64 + c * 4;
        unsigned st = sb0 + SM_ST;
        cpa16(st + off,         &g_kh[gi]);
        cpa16(st + 16384 + off, &g_kl[gi]);
        cpa16(st + 32768 + off, &g_vh[gi]);
        cpa16(st + 49152 + off, &g_vl[gi]);
    }
    cpa_commit();
    cpa_wait0();
    __syncthreads();

    int am = (lane >> 3) & 1, ar = lane & 7, ac = lane >> 4;

    // hoisted Q fragments (invariant across jt)
    unsigned Qh[8][4], Ql[8][4];
    #pragma unroll
    for (int ks = 0; ks < 8; ks++) {
        int row = qr0 + am * 8 + ar, ch = ks * 2 + ac;
        unsigned a = sb0 + SM_QH + row * 256 + ((ch ^ (row & 7)) << 4);
        ldsm4(Qh[ks], a); ldsm4(Ql[ks], a + 16384);
    }

    float O[16][4];
    #pragma unroll
    for (int o = 0; o < 16; o++) { O[o][0]=0;O[o][1]=0;O[o][2]=0;O[o][3]=0; }
    float lg = 0.f, lg8 = 0.f;
    const int iA = i0 + qr0 + g;

    for (int jt = 0; jt <= it; jt++) {
        if (jt > 0) { cpa_wait0(); __syncthreads(); }
        unsigned st = sb0 + SM_ST + (jt & 1) * SM_STSZ;
        if (jt < it) {
            unsigned sn = sb0 + SM_ST + ((jt + 1) & 1) * SM_STSZ;
            size_t gb = hb + (size_t)(jt + 1) * 64 * 64;
            #pragma unroll
            for (int i = 0; i < 4; i++) {
                int e = tid + i * 256;
                int r = e >> 4, c = e & 15;
                unsigned off = (unsigned)(r * 256 + ((c ^ (r & 7)) << 4));
                size_t gi = gb + (size_t)r * 64 + c * 4;
                cpa16(sn + off,         &g_kh[gi]);
                cpa16(sn + 16384 + off, &g_kl[gi]);
                cpa16(sn + 32768 + off, &g_vh[gi]);
                cpa16(sn + 49152 + off, &g_vl[gi]);
            }
            cpa_commit();
        }

        // ---- QK (3-term split): S[16 rows][32 keys] per warp ----
        float S[4][4];
        #pragma unroll
        for (int n = 0; n < 4; n++) { S[n][0]=0;S[n][1]=0;S[n][2]=0;S[n][3]=0; }

        #pragma unroll
        for (int ks = 0; ks < 8; ks++) {
            #pragma unroll
            for (int kt = 0; kt < 2; kt++) {
                unsigned bh[4], bl[4];
                int row = kh * 32 + kt * 16 + am * 8 + ar, ch = ks * 2 + ac;
                unsigned a = st + row * 256 + ((ch ^ (row & 7)) << 4);
                ldsm4(bh, a); ldsm4(bl, a + 16384);
                mma16(S[kt*2],   Qh[ks], bh[0], bh[2]);
                mma16(S[kt*2],   Qh[ks], bl[0], bl[2]);
                mma16(S[kt*2],   Ql[ks], bh[0], bh[2]);
                mma16(S[kt*2+1], Qh[ks], bh[1], bh[3]);
                mma16(S[kt*2+1], Qh[ks], bl[1], bl[3]);
                mma16(S[kt*2+1], Ql[ks], bh[1], bh[3]);
            }
        }

        // ---- mask + exp (max-free); l from exact p ----
        int jb = jt * 64 + kh * 32;
        unsigned vw = vbm[jb >> 5];
        #pragma unroll
        for (int n = 0; n < 4; n++) {
            int cb = n * 8 + 2 * t;
            #pragma unroll
            for (int e = 0; e < 4; e++) {
                int roff = (e >> 1) * 8, b = e & 1;
                int j = jb + cb + b;
                int d = iA + roff - j;
                unsigned sbit = (d >= 0) ? ((sbm[d >> 5] >> (d & 31)) & 1u) : 0u;
                bool ok = (d >= 0) && (((vw >> (cb + b)) & 1u) || sbit);
                float p = ok ? __expf(S[n][e]) : 0.f;
                S[n][e] = p;
                if (e < 2) lg += p; else lg8 += p;
            }
        }

        // ---- PV (3-term: Ph*Vh + Ph*Vl + Pl*Vh) ----
        #pragma unroll
        for (int kp = 0; kp < 2; kp++) {
            unsigned aph[4], apl[4];
            #pragma unroll
            for (int u = 0; u < 4; u++) {
                float x = S[kp*2 + (u>>1)][(u&1)*2], y = S[kp*2 + (u>>1)][(u&1)*2+1];
                float hx = __bfloat162float(__float2bfloat16_rn(x));
                float hy = __bfloat162float(__float2bfloat16_rn(y));
                aph[u] = pk2(hx, hy);
                apl[u] = pk2(x - hx, y - hy);
            }
            #pragma unroll
            for (int n2 = 0; n2 < 8; n2++) {
                unsigned vh4[4], vl4[4];
                int row = kh * 32 + kp * 16 + am * 8 + ar, ch = n2 * 2 + ac;
                unsigned a = st + 32768 + row * 256 + ((ch ^ (row & 7)) << 4);
                ldsm4t(vh4, a); ldsm4t(vl4, a + 16384);
                mma16(O[n2*2],   aph, vh4[0], vh4[1]);
                mma16(O[n2*2],   aph, vl4[0], vl4[1]);
                mma16(O[n2*2],   apl, vh4[0], vh4[1]);
                mma16(O[n2*2+1], aph, vh4[2], vh4[3]);
                mma16(O[n2*2+1], aph, vl4[2], vl4[3]);
                mma16(O[n2*2+1], apl, vh4[2], vh4[3]);
            }
        }
    }

    // ---- epilogue: reduce across key-halves via smem ----
    __syncthreads();
    float* Op = (float*)(smem + SM_ST);
    float* lp = (float*)(smem + SM_ST + 32768);
    lg  += __shfl_xor_sync(0xffffffffu, lg, 1);  lg  += __shfl_xor_sync(0xffffffffu, lg, 2);
    lg8 += __shfl_xor_sync(0xffffffffu, lg8, 1); lg8 += __shfl_xor_sync(0xffffffffu, lg8, 2);
    if (kh == 1) {
        #pragma unroll
        for (int o = 0; o < 16; o++) {
            *(float2*)&Op[(qr0+g)*128   + o*8 + 2*t] = make_float2(O[o][0], O[o][1]);
            *(float2*)&Op[(qr0+g+8)*128 + o*8 + 2*t] = make_float2(O[o][2], O[o][3]);
        }
        if (t == 0) { lp[qr0+g] = lg; lp[qr0+g+8] = lg8; }
    }
    __syncthreads();
    if (kh == 0) {
        float inv0 = 1.0f / (lg  + lp[qr0+g]);
        float inv1 = 1.0f / (lg8 + lp[qr0+g+8]);
        size_t ob = (size_t)h * SEQ * DH;
        #pragma unroll
        for (int o = 0; o < 16; o++) {
            float2 p0 = *(float2*)&Op[(qr0+g)*128   + o*8 + 2*t];
            float2 p1 = *(float2*)&Op[(qr0+g+8)*128 + o*8 + 2*t];
            *(float2*)&out[ob + (size_t)(i0+qr0+g)*DH   + o*8 + 2*t] =
                make_float2((O[o][0] + p0.x) * inv0, (O[o][1] + p0.y) * inv0);
            *(float2*)&out[ob + (size_t)(i0+qr0+g+8)*DH + o*8 + 2*t] =
                make_float2((O[o][2] + p1.x) * inv1, (O[o][3] + p1.y) * inv1);
        }
    }
}

// ---------------- launch ----------------
extern "C" void kernel_launch(void* const* d_in, const int* in_sizes, int n_in,
                              void* d_out, int out_size) {
    const float* q = (const float*)d_in[0];
    const float* k = (const float*)d_in[1];
    const float* v = (const float*)d_in[2];
    float* out = (float*)d_out;

    prep_kernel<<<(NPAIR + 255) / 256, 256>>>(q, k, v);

    int psm = (64 * QS_STRIDE + 128 * 128) * 4;
    cudaFuncSetAttribute(pattern_kernel, cudaFuncAttributeMaxDynamicSharedMemorySize, psm);
    pattern_kernel<<<dim3(SEQ / 128, NH), 256, psm>>>(q, k);
    rowsum_kernel<<<NH * LQ, 128>>>();
    reduce_kernel<<<dim3(NH, SEQ / 256), 256>>>();
    topk_kernel<<<dim3(2, NH), 256>>>();

    cudaFuncSetAttribute(flash_mma_kernel, cudaFuncAttributeMaxDynamicSharedMemorySize, FL_BYTES);
    flash_mma_kernel<<<64 * NH, 256, FL_BYTES>>>(out);
}

// round 8
// speedup vs baseline: 3.1396x; 1.1856x over previous
#include <cuda_runtime.h>
#include <cuda_fp16.h>
#include <math.h>
#include <float.h>

#define NH 8
#define SEQ 4096
#define DH 128
#define LQ 64
#define VTOPK 1024
#define STOPK 2048
#define FORCE_V 30
#define FORCE_S 100
#define SCALE 0.08838834764831845f
#define NW (SEQ / 32)
#define QS_STRIDE 132
#define NPAIR (NH * SEQ * DH / 2)

// ---------------- device scratch ----------------
__device__ float    g_probs[NH * LQ * SEQ];
__device__ float    g_rowinv[NH * LQ];
__device__ float    g_vert [NH * SEQ];
__device__ float    g_slash[NH * SEQ];
__device__ unsigned g_vbits[NH * NW];
__device__ unsigned g_sbits[NH * NW];
// fp16 hi/lo splits, 2 elems packed per u32 (low = even index)
__device__ unsigned g_qh[NPAIR], g_ql[NPAIR];
__device__ unsigned g_kh[NPAIR], g_kl[NPAIR];
__device__ unsigned g_vh[NPAIR];

// ---------------- helpers ----------------
__device__ __forceinline__ void cpa16(unsigned dst, const void* src) {
    asm volatile("cp.async.cg.shared.global [%0], [%1], 16;\n" :: "r"(dst), "l"(src));
}
__device__ __forceinline__ void cpa_commit() { asm volatile("cp.async.commit_group;\n" ::); }
__device__ __forceinline__ void cpa_wait0()  { asm volatile("cp.async.wait_group 0;\n" ::); }

__device__ __forceinline__ void ldsm4(unsigned* r, unsigned a) {
    asm volatile("ldmatrix.sync.aligned.m8n8.x4.shared.b16 {%0,%1,%2,%3}, [%4];"
        : "=r"(r[0]), "=r"(r[1]), "=r"(r[2]), "=r"(r[3]) : "r"(a));
}
__device__ __forceinline__ void ldsm4t(unsigned* r, unsigned a) {
    asm volatile("ldmatrix.sync.aligned.m8n8.x4.trans.shared.b16 {%0,%1,%2,%3}, [%4];"
        : "=r"(r[0]), "=r"(r[1]), "=r"(r[2]), "=r"(r[3]) : "r"(a));
}
__device__ __forceinline__ void mma16(float* d, const unsigned* a, unsigned b0, unsigned b1) {
    asm volatile("mma.sync.aligned.m16n8k16.row.col.f32.f16.f16.f32 "
        "{%0,%1,%2,%3}, {%4,%5,%6,%7}, {%8,%9}, {%0,%1,%2,%3};"
        : "+f"(d[0]), "+f"(d[1]), "+f"(d[2]), "+f"(d[3])
        : "r"(a[0]), "r"(a[1]), "r"(a[2]), "r"(a[3]), "r"(b0), "r"(b1));
}
__device__ __forceinline__ unsigned pk2h(float x, float y) {
    __half2 t = __floats2half2_rn(x, y);
    return *(unsigned*)&t;
}

// ---------------- prep: split q*scale, k into fp16 hi/lo; v -> fp16 ----------------
__global__ void prep_kernel(const float* __restrict__ q, const float* __restrict__ k,
                            const float* __restrict__ v) {
    int i = blockIdx.x * 256 + threadIdx.x;
    if (i >= NPAIR) return;
    float2 a = ((const float2*)q)[i];
    a.x *= SCALE; a.y *= SCALE;
    float hx = __half2float(__float2half_rn(a.x));
    float hy = __half2float(__float2half_rn(a.y));
    g_qh[i] = pk2h(hx, hy); g_ql[i] = pk2h(a.x - hx, a.y - hy);
    a = ((const float2*)k)[i];
    hx = __half2float(__float2half_rn(a.x));
    hy = __half2float(__float2half_rn(a.y));
    g_kh[i] = pk2h(hx, hy); g_kl[i] = pk2h(a.x - hx, a.y - hy);
    a = ((const float2*)v)[i];
    g_vh[i] = pk2h(a.x, a.y);
}

// ---------------- kernel A: exp-scores for last 64 queries ----------------
__global__ void pattern_kernel(const float* __restrict__ q, const float* __restrict__ k) {
    extern __shared__ float psm[];
    float* Qs = psm;
    float* Ks = Qs + 64 * QS_STRIDE;
    int h = blockIdx.y, j0 = blockIdx.x * 128;
    int tid = threadIdx.x, ty = tid >> 4, tx = tid & 15;

    for (int e = tid; e < 64 * 32; e += 256) {
        int r = e >> 5, c = e & 31;
        float4 t = *(const float4*)&q[((size_t)(h * SEQ + SEQ - LQ + r)) * DH + (c << 2)];
        t.x *= SCALE; t.y *= SCALE; t.z *= SCALE; t.w *= SCALE;
        *(float4*)&Qs[r * QS_STRIDE + (c << 2)] = t;
    }
    for (int e = tid; e < 128 * 32; e += 256) {
        int r = e >> 5, c = e & 31;
        *(float4*)&Ks[r * 128 + ((c ^ (r >> 2)) << 2)] =
            *(const float4*)&k[((size_t)(h * SEQ + j0 + r)) * DH + (c << 2)];
    }
    __syncthreads();

    float s[4][8];
    #pragma unroll
    for (int a = 0; a < 4; a++)
        #pragma unroll
        for (int b = 0; b < 8; b++) s[a][b] = 0.f;

    #pragma unroll 4
    for (int c = 0; c < 32; c++) {
        float4 qv[4], kv[8];
        #pragma unroll
        for (int a = 0; a < 4; a++)
            qv[a] = *(const float4*)&Qs[(ty * 4 + a) * QS_STRIDE + (c << 2)];
        #pragma unroll
        for (int b = 0; b < 8; b++) {
            int r = tx * 8 + b;
            kv[b] = *(const float4*)&Ks[r * 128 + ((c ^ (r >> 2)) << 2)];
        }
        #pragma unroll
        for (int a = 0; a < 4; a++)
            #pragma unroll
            for (int b = 0; b < 8; b++)
                s[a][b] += qv[a].x * kv[b].x + qv[a].y * kv[b].y
                         + qv[a].z * kv[b].z + qv[a].w * kv[b].w;
    }
    #pragma unroll
    for (int a = 0; a < 4; a++) {
        int row = ty * 4 + a, qpos = SEQ - LQ + row;
        float p[8];
        #pragma unroll
        for (int b = 0; b < 8; b++) {
            int j = j0 + tx * 8 + b;
            p[b] = (j <= qpos) ? __expf(s[a][b]) : 0.f;
        }
        float* dst = &g_probs[((size_t)(h * LQ + row)) * SEQ + j0 + tx * 8];
        *(float4*)&dst[0] = make_float4(p[0], p[1], p[2], p[3]);
        *(float4*)&dst[4] = make_float4(p[4], p[5], p[6], p[7]);
    }
}

// ---------------- kernel B1: deterministic row sums ----------------
__global__ void rowsum_kernel() {
    int b = blockIdx.x;
    int h = b >> 6, r = b & 63;
    const float* rowp = &g_probs[((size_t)(h * LQ + r)) * SEQ];
    int tid = threadIdx.x;              // 128
    float s = 0.f;
    for (int j = tid; j < SEQ; j += 128) s += rowp[j];
    __shared__ float red[128];
    red[tid] = s; __syncthreads();
    #pragma unroll
    for (int st = 64; st > 0; st >>= 1) {
        if (tid < st) red[tid] += red[tid + st];
        __syncthreads();
    }
    if (tid == 0) g_rowinv[h * LQ + r] = 1.0f / red[0];
}

// ---------------- kernel B2: vertical + slash (slice-parallel) ----------------
__global__ void reduce_kernel() {
    int h = blockIdx.x, seg = blockIdx.y;
    int tid = threadIdx.x;              // 256
    __shared__ float inv[LQ];
    if (tid < LQ) inv[tid] = g_rowinv[h * LQ + tid];
    __syncthreads();
    const float* pb = &g_probs[(size_t)h * LQ * SEQ];
    int j = seg * 256 + tid;
    float s = 0.f;
    #pragma unroll 8
    for (int lq = 0; lq < LQ; lq++) s += pb[(size_t)lq * SEQ + j] * inv[lq];
    g_vert[h * SEQ + j] = (j < FORCE_V) ? INFINITY : s;
    float t = 0.f;
    #pragma unroll 8
    for (int lq = 0; lq < LQ; lq++) {
        int idx = (SEQ - LQ) + lq - j;
        if (idx >= 0) t += pb[(size_t)lq * SEQ + idx] * inv[lq];
    }
    g_slash[h * SEQ + j] = (j < FORCE_S) ? INFINITY : t;
}

// ---------------- kernel C: exact top-k via radix select (jax tie-break) ----------------
__global__ void topk_kernel() {
    int which = blockIdx.x, h = blockIdx.y;
    const float* arr = which ? &g_slash[h * SEQ] : &g_vert[h * SEQ];
    unsigned*   bits = which ? &g_sbits[h * NW]  : &g_vbits[h * NW];
    const int K = which ? STOPK : VTOPK;

    __shared__ unsigned vals[SEQ];
    __shared__ unsigned hist[256];
    __shared__ unsigned s_prefix;
    __shared__ int s_rem;
    __shared__ unsigned gtw[NW], eqw[NW], wcnt[NW], psum[NW];
    int tid = threadIdx.x;              // 256

    for (int i = tid; i < SEQ; i += 256) vals[i] = __float_as_uint(arr[i]);
    __syncthreads();

    unsigned prefix = 0; int remaining = K;
    #pragma unroll
    for (int pass = 3; pass >= 0; pass--) {
        int shift = pass * 8;
        hist[tid] = 0u;
        __syncthreads();
        unsigned long long ph = (unsigned long long)prefix >> (shift + 8);
        for (int i = tid; i < SEQ; i += 256) {
            unsigned v = vals[i];
            if (((unsigned long long)v >> (shift + 8)) == ph)
                atomicAdd(&hist[(v >> shift) & 255u], 1u);
        }
        __syncthreads();
        if (tid == 0) {
            int cum = 0, b = 255;
            for (; b > 0; b--) {
                cum += (int)hist[b];
                if (cum >= remaining) break;
            }
            if (cum < remaining) cum += (int)hist[0];
            s_rem = remaining - (cum - (int)hist[b]);
            s_prefix = prefix | ((unsigned)b << shift);
        }
        __syncthreads();
        prefix = s_prefix; remaining = s_rem;
        __syncthreads();
    }

    if (tid < NW) {
        unsigned gm = 0, em = 0;
        #pragma unroll 8
        for (int b = 0; b < 32; b++) {
            unsigned v = vals[tid * 32 + b];
            gm |= (v > prefix ? 1u : 0u) << b;
            em |= (v == prefix ? 1u : 0u) << b;
        }
        gtw[tid] = gm; eqw[tid] = em; wcnt[tid] = __popc(em);
    }
    __syncthreads();
    if (tid == 0) {
        unsigned run = 0;
        for (int w = 0; w < NW; w++) { psum[w] = run; run += wcnt[w]; }
    }
    __syncthreads();
    if (tid < NW) {
        unsigned em = eqw[tid], sel = 0;
        int rank = (int)psum[tid];
        while (em) {
            int b = __ffs(em) - 1;
            if (rank < remaining) sel |= 1u << b;
            rank++;
            em &= em - 1;
        }
        bits[tid] = gtw[tid] | sel;
    }
}

// ---------------- kernel D: tensor-core masked flash attention ----------------
// smem: QH 0..16K, QL 16K..32K, vb@32768, sb@33280,
// stages @34816: each 48K = Kh(16K) Kl(16K) Vh(16K). total 133120.
#define SM_QH 0
#define SM_QL 16384
#define SM_VB 32768
#define SM_SB 33280
#define SM_ST 34816
#define SM_STSZ 49152
#define FL_BYTES (SM_ST + 2 * SM_STSZ)

__global__ void __launch_bounds__(256, 1)
flash_mma_kernel(float* __restrict__ out) {
    extern __shared__ unsigned char smem[];
    const unsigned sb0 = (unsigned)__cvta_generic_to_shared(smem);
    unsigned* vbm = (unsigned*)(smem + SM_VB);
    unsigned* sbm = (unsigned*)(smem + SM_SB);

    int bid = blockIdx.x;
    int h   = bid & 7;
    int it  = 63 - (bid >> 3);
    int tid = threadIdx.x, lane = tid & 31, w = tid >> 5;
    int qw = w & 3, kh = w >> 2;
    int g = lane >> 2, t = lane & 3;
    const int i0 = it * 64, qr0 = qw * 16;
    const size_t hb = (size_t)h * SEQ * 64;

    if (tid < NW)            vbm[tid]      = g_vbits[h * NW + tid];
    else if (tid < 2 * NW)   sbm[tid - NW] = g_sbits[h * NW + tid - NW];

    // Q tiles + stage 0, one commit group
    #pragma unroll
    for (int i = 0; i < 4; i++) {
        int e = tid + i * 256;
        int r = e >> 4, c = e & 15;
        unsigned off = (unsigned)(r * 256 + ((c ^ (r & 7)) << 4));
        size_t gq = hb + (size_t)(i0 + r) * 64 + c * 4;
        cpa16(sb0 + SM_QH + off, &g_qh[gq]);
        cpa16(sb0 + SM_QL + off, &g_ql[gq]);
        size_t gi = hb + (size_t)r * 64 + c * 4;
        unsigned st = sb0 + SM_ST;
        cpa16(st + off,         &g_kh[gi]);
        cpa16(st + 16384 + off, &g_kl[gi]);
        cpa16(st + 32768 + off, &g_vh[gi]);
    }
    cpa_commit();
    cpa_wait0();
    __syncthreads();

    int am = (lane >> 3) & 1, ar = lane & 7, ac = lane >> 4;

    // hoisted Q fragments (invariant across jt)
    unsigned Qh[8][4], Ql[8][4];
    #pragma unroll
    for (int ks = 0; ks < 8; ks++) {
        int row = qr0 + am * 8 + ar, ch = ks * 2 + ac;
        unsigned a = sb0 + SM_QH + row * 256 + ((ch ^ (row & 7)) << 4);
        ldsm4(Qh[ks], a); ldsm4(Ql[ks], a + 16384);
    }

    float O[16][4];
    #pragma unroll
    for (int o = 0; o < 16; o++) { O[o][0]=0;O[o][1]=0;O[o][2]=0;O[o][3]=0; }
    float lg = 0.f, lg8 = 0.f;
    const int iA = i0 + qr0 + g;

    for (int jt = 0; jt <= it; jt++) {
        if (jt > 0) { cpa_wait0(); __syncthreads(); }
        unsigned st = sb0 + SM_ST + (jt & 1) * SM_STSZ;
        if (jt < it) {
            unsigned sn = sb0 + SM_ST + ((jt + 1) & 1) * SM_STSZ;
            size_t gb = hb + (size_t)(jt + 1) * 64 * 64;
            #pragma unroll
            for (int i = 0; i < 4; i++) {
                int e = tid + i * 256;
                int r = e >> 4, c = e & 15;
                unsigned off = (unsigned)(r * 256 + ((c ^ (r & 7)) << 4));
                size_t gi = gb + (size_t)r * 64 + c * 4;
                cpa16(sn + off,         &g_kh[gi]);
                cpa16(sn + 16384 + off, &g_kl[gi]);
                cpa16(sn + 32768 + off, &g_vh[gi]);
            }
            cpa_commit();
        }

        // ---- QK (3-term split): S[16 rows][32 keys] per warp ----
        float S[4][4];
        #pragma unroll
        for (int n = 0; n < 4; n++) { S[n][0]=0;S[n][1]=0;S[n][2]=0;S[n][3]=0; }

        #pragma unroll
        for (int ks = 0; ks < 8; ks++) {
            #pragma unroll
            for (int kt = 0; kt < 2; kt++) {
                unsigned bh[4], bl[4];
                int row = kh * 32 + kt * 16 + am * 8 + ar, ch = ks * 2 + ac;
                unsigned a = st + row * 256 + ((ch ^ (row & 7)) << 4);
                ldsm4(bh, a); ldsm4(bl, a + 16384);
                mma16(S[kt*2],   Qh[ks], bh[0], bh[2]);
                mma16(S[kt*2],   Qh[ks], bl[0], bl[2]);
                mma16(S[kt*2],   Ql[ks], bh[0], bh[2]);
                mma16(S[kt*2+1], Qh[ks], bh[1], bh[3]);
                mma16(S[kt*2+1], Qh[ks], bl[1], bl[3]);
                mma16(S[kt*2+1], Ql[ks], bh[1], bh[3]);
            }
        }

        // ---- mask + exp (max-free); round P to fp16, l from rounded p ----
        int jb = jt * 64 + kh * 32;
        unsigned vw = vbm[jb >> 5];
        #pragma unroll
        for (int n = 0; n < 4; n++) {
            int cb = n * 8 + 2 * t;
            #pragma unroll
            for (int e = 0; e < 4; e++) {
                int roff = (e >> 1) * 8, b = e & 1;
                int j = jb + cb + b;
                int d = iA + roff - j;
                unsigned sbit = (d >= 0) ? ((sbm[d >> 5] >> (d & 31)) & 1u) : 0u;
                bool ok = (d >= 0) && (((vw >> (cb + b)) & 1u) || sbit);
                float p = ok ? __expf(S[n][e]) : 0.f;
                p = __half2float(__float2half_rn(p));
                S[n][e] = p;
                if (e < 2) lg += p; else lg8 += p;
            }
        }

        // ---- PV (single-term fp16 P x fp16 V) ----
        #pragma unroll
        for (int kp = 0; kp < 2; kp++) {
            unsigned aph[4];
            #pragma unroll
            for (int u = 0; u < 4; u++) {
                aph[u] = pk2h(S[kp*2 + (u>>1)][(u&1)*2], S[kp*2 + (u>>1)][(u&1)*2+1]);
            }
            #pragma unroll
            for (int n2 = 0; n2 < 8; n2++) {
                unsigned vh4[4];
                int row = kh * 32 + kp * 16 + am * 8 + ar, ch = n2 * 2 + ac;
                unsigned a = st + 32768 + row * 256 + ((ch ^ (row & 7)) << 4);
                ldsm4t(vh4, a);
                mma16(O[n2*2],   aph, vh4[0], vh4[1]);
                mma16(O[n2*2+1], aph, vh4[2], vh4[3]);
            }
        }
    }

    // ---- epilogue: reduce across key-halves via smem ----
    __syncthreads();
    float* Op = (float*)(smem + SM_ST);
    float* lp = (float*)(smem + SM_ST + 32768);
    lg  += __shfl_xor_sync(0xffffffffu, lg, 1);  lg  += __shfl_xor_sync(0xffffffffu, lg, 2);
    lg8 += __shfl_xor_sync(0xffffffffu, lg8, 1); lg8 += __shfl_xor_sync(0xffffffffu, lg8, 2);
    if (kh == 1) {
        #pragma unroll
        for (int o = 0; o < 16; o++) {
            *(float2*)&Op[(qr0+g)*128   + o*8 + 2*t] = make_float2(O[o][0], O[o][1]);
            *(float2*)&Op[(qr0+g+8)*128 + o*8 + 2*t] = make_float2(O[o][2], O[o][3]);
        }
        if (t == 0) { lp[qr0+g] = lg; lp[qr0+g+8] = lg8; }
    }
    __syncthreads();
    if (kh == 0) {
        float inv0 = 1.0f / (lg  + lp[qr0+g]);
        float inv1 = 1.0f / (lg8 + lp[qr0+g+8]);
        size_t ob = (size_t)h * SEQ * DH;
        #pragma unroll
        for (int o = 0; o < 16; o++) {
            float2 p0 = *(float2*)&Op[(qr0+g)*128   + o*8 + 2*t];
            float2 p1 = *(float2*)&Op[(qr0+g+8)*128 + o*8 + 2*t];
            *(float2*)&out[ob + (size_t)(i0+qr0+g)*DH   + o*8 + 2*t] =
                make_float2((O[o][0] + p0.x) * inv0, (O[o][1] + p0.y) * inv0);
            *(float2*)&out[ob + (size_t)(i0+qr0+g+8)*DH + o*8 + 2*t] =
                make_float2((O[o][2] + p1.x) * inv1, (O[o][3] + p1.y) * inv1);
        }
    }
}

// ---------------- launch ----------------
extern "C" void kernel_launch(void* const* d_in, const int* in_sizes, int n_in,
                              void* d_out, int out_size) {
    const float* q = (const float*)d_in[0];
    const float* k = (const float*)d_in[1];
    const float* v = (const float*)d_in[2];
    float* out = (float*)d_out;

    prep_kernel<<<(NPAIR + 255) / 256, 256>>>(q, k, v);

    int psm = (64 * QS_STRIDE + 128 * 128) * 4;
    cudaFuncSetAttribute(pattern_kernel, cudaFuncAttributeMaxDynamicSharedMemorySize, psm);
    pattern_kernel<<<dim3(SEQ / 128, NH), 256, psm>>>(q, k);
    rowsum_kernel<<<NH * LQ, 128>>>();
    reduce_kernel<<<dim3(NH, SEQ / 256), 256>>>();
    topk_kernel<<<dim3(2, NH), 256>>>();

    cudaFuncSetAttribute(flash_mma_kernel, cudaFuncAttributeMaxDynamicSharedMemorySize, FL_BYTES);
    flash_mma_kernel<<<64 * NH, 256, FL_BYTES>>>(out);
}

// round 9
// speedup vs baseline: 3.8697x; 1.2325x over previous
#include <cuda_runtime.h>
#include <cuda_fp16.h>
#include <math.h>
#include <float.h>

#define NH 8
#define SEQ 4096
#define DH 128
#define LQ 64
#define VTOPK 1024
#define STOPK 2048
#define FORCE_V 30
#define FORCE_S 100
#define SCALE 0.08838834764831845f
#define NW (SEQ / 32)
#define QS_STRIDE 132
#define NPAIR (NH * SEQ * DH / 2)

// ---------------- device scratch ----------------
__device__ float    g_probs[NH * LQ * SEQ];
__device__ float    g_rowinv[NH * LQ];
__device__ float    g_vert [NH * SEQ];
__device__ float    g_slash[NH * SEQ];
__device__ unsigned g_vbits[NH * NW];
__device__ unsigned g_sbits[NH * NW];
// fp16, 2 elems packed per u32 (low = even index)
__device__ unsigned g_q[NPAIR], g_k[NPAIR], g_v[NPAIR];

// ---------------- helpers ----------------
__device__ __forceinline__ void cpa16(unsigned dst, const void* src) {
    asm volatile("cp.async.cg.shared.global [%0], [%1], 16;\n" :: "r"(dst), "l"(src));
}
__device__ __forceinline__ void cpa_commit() { asm volatile("cp.async.commit_group;\n" ::); }
__device__ __forceinline__ void cpa_wait0()  { asm volatile("cp.async.wait_group 0;\n" ::); }

__device__ __forceinline__ void ldsm4(unsigned* r, unsigned a) {
    asm volatile("ldmatrix.sync.aligned.m8n8.x4.shared.b16 {%0,%1,%2,%3}, [%4];"
        : "=r"(r[0]), "=r"(r[1]), "=r"(r[2]), "=r"(r[3]) : "r"(a));
}
__device__ __forceinline__ void ldsm4t(unsigned* r, unsigned a) {
    asm volatile("ldmatrix.sync.aligned.m8n8.x4.trans.shared.b16 {%0,%1,%2,%3}, [%4];"
        : "=r"(r[0]), "=r"(r[1]), "=r"(r[2]), "=r"(r[3]) : "r"(a));
}
__device__ __forceinline__ void mma16(float* d, const unsigned* a, unsigned b0, unsigned b1) {
    asm volatile("mma.sync.aligned.m16n8k16.row.col.f32.f16.f16.f32 "
        "{%0,%1,%2,%3}, {%4,%5,%6,%7}, {%8,%9}, {%0,%1,%2,%3};"
        : "+f"(d[0]), "+f"(d[1]), "+f"(d[2]), "+f"(d[3])
        : "r"(a[0]), "r"(a[1]), "r"(a[2]), "r"(a[3]), "r"(b0), "r"(b1));
}
__device__ __forceinline__ unsigned pk2h(float x, float y) {
    __half2 t = __floats2half2_rn(x, y);
    return *(unsigned*)&t;
}

// ---------------- prep: q*scale, k, v -> fp16 ----------------
__global__ void prep_kernel(const float* __restrict__ q, const float* __restrict__ k,
                            const float* __restrict__ v) {
    int i = blockIdx.x * 256 + threadIdx.x;
    if (i >= NPAIR) return;
    float2 a = ((const float2*)q)[i];
    g_q[i] = pk2h(a.x * SCALE, a.y * SCALE);
    a = ((const float2*)k)[i];
    g_k[i] = pk2h(a.x, a.y);
    a = ((const float2*)v)[i];
    g_v[i] = pk2h(a.x, a.y);
}

// ---------------- kernel A: exp-scores for last 64 queries ----------------
__global__ void pattern_kernel(const float* __restrict__ q, const float* __restrict__ k) {
    extern __shared__ float psm[];
    float* Qs = psm;
    float* Ks = Qs + 64 * QS_STRIDE;
    int h = blockIdx.y, j0 = blockIdx.x * 128;
    int tid = threadIdx.x, ty = tid >> 4, tx = tid & 15;

    for (int e = tid; e < 64 * 32; e += 256) {
        int r = e >> 5, c = e & 31;
        float4 t = *(const float4*)&q[((size_t)(h * SEQ + SEQ - LQ + r)) * DH + (c << 2)];
        t.x *= SCALE; t.y *= SCALE; t.z *= SCALE; t.w *= SCALE;
        *(float4*)&Qs[r * QS_STRIDE + (c << 2)] = t;
    }
    for (int e = tid; e < 128 * 32; e += 256) {
        int r = e >> 5, c = e & 31;
        *(float4*)&Ks[r * 128 + ((c ^ (r >> 2)) << 2)] =
            *(const float4*)&k[((size_t)(h * SEQ + j0 + r)) * DH + (c << 2)];
    }
    __syncthreads();

    float s[4][8];
    #pragma unroll
    for (int a = 0; a < 4; a++)
        #pragma unroll
        for (int b = 0; b < 8; b++) s[a][b] = 0.f;

    #pragma unroll 4
    for (int c = 0; c < 32; c++) {
        float4 qv[4], kv[8];
        #pragma unroll
        for (int a = 0; a < 4; a++)
            qv[a] = *(const float4*)&Qs[(ty * 4 + a) * QS_STRIDE + (c << 2)];
        #pragma unroll
        for (int b = 0; b < 8; b++) {
            int r = tx * 8 + b;
            kv[b] = *(const float4*)&Ks[r * 128 + ((c ^ (r >> 2)) << 2)];
        }
        #pragma unroll
        for (int a = 0; a < 4; a++)
            #pragma unroll
            for (int b = 0; b < 8; b++)
                s[a][b] += qv[a].x * kv[b].x + qv[a].y * kv[b].y
                         + qv[a].z * kv[b].z + qv[a].w * kv[b].w;
    }
    #pragma unroll
    for (int a = 0; a < 4; a++) {
        int row = ty * 4 + a, qpos = SEQ - LQ + row;
        float p[8];
        #pragma unroll
        for (int b = 0; b < 8; b++) {
            int j = j0 + tx * 8 + b;
            p[b] = (j <= qpos) ? __expf(s[a][b]) : 0.f;
        }
        float* dst = &g_probs[((size_t)(h * LQ + row)) * SEQ + j0 + tx * 8];
        *(float4*)&dst[0] = make_float4(p[0], p[1], p[2], p[3]);
        *(float4*)&dst[4] = make_float4(p[4], p[5], p[6], p[7]);
    }
}

// ---------------- kernel B1: deterministic row sums ----------------
__global__ void rowsum_kernel() {
    int b = blockIdx.x;
    int h = b >> 6, r = b & 63;
    const float* rowp = &g_probs[((size_t)(h * LQ + r)) * SEQ];
    int tid = threadIdx.x;              // 128
    float s = 0.f;
    for (int j = tid; j < SEQ; j += 128) s += rowp[j];
    __shared__ float red[128];
    red[tid] = s; __syncthreads();
    #pragma unroll
    for (int st = 64; st > 0; st >>= 1) {
        if (tid < st) red[tid] += red[tid + st];
        __syncthreads();
    }
    if (tid == 0) g_rowinv[h * LQ + r] = 1.0f / red[0];
}

// ---------------- kernel B2: vertical + slash ----------------
__global__ void reduce_kernel() {
    int h = blockIdx.x, seg = blockIdx.y;
    int tid = threadIdx.x;              // 256
    __shared__ float inv[LQ];
    if (tid < LQ) inv[tid] = g_rowinv[h * LQ + tid];
    __syncthreads();
    const float* pb = &g_probs[(size_t)h * LQ * SEQ];
    int j = seg * 256 + tid;
    float s = 0.f;
    #pragma unroll 8
    for (int lq = 0; lq < LQ; lq++) s += pb[(size_t)lq * SEQ + j] * inv[lq];
    g_vert[h * SEQ + j] = (j < FORCE_V) ? INFINITY : s;
    float t = 0.f;
    #pragma unroll 8
    for (int lq = 0; lq < LQ; lq++) {
        int idx = (SEQ - LQ) + lq - j;
        if (idx >= 0) t += pb[(size_t)lq * SEQ + idx] * inv[lq];
    }
    g_slash[h * SEQ + j] = (j < FORCE_S) ? INFINITY : t;
}

// ---------------- kernel C: exact top-k via radix select ----------------
__global__ void topk_kernel() {
    int which = blockIdx.x, h = blockIdx.y;
    const float* arr = which ? &g_slash[h * SEQ] : &g_vert[h * SEQ];
    unsigned*   bits = which ? &g_sbits[h * NW]  : &g_vbits[h * NW];
    const int K = which ? STOPK : VTOPK;

    __shared__ unsigned vals[SEQ];
    __shared__ unsigned hist[256];
    __shared__ unsigned s_prefix;
    __shared__ int s_rem;
    __shared__ unsigned gtw[NW], eqw[NW], wcnt[NW], psum[NW];
    int tid = threadIdx.x;              // 256

    for (int i = tid; i < SEQ; i += 256) vals[i] = __float_as_uint(arr[i]);
    __syncthreads();

    unsigned prefix = 0; int remaining = K;
    #pragma unroll
    for (int pass = 3; pass >= 0; pass--) {
        int shift = pass * 8;
        hist[tid] = 0u;
        __syncthreads();
        unsigned long long ph = (unsigned long long)prefix >> (shift + 8);
        for (int i = tid; i < SEQ; i += 256) {
            unsigned v = vals[i];
            if (((unsigned long long)v >> (shift + 8)) == ph)
                atomicAdd(&hist[(v >> shift) & 255u], 1u);
        }
        __syncthreads();
        if (tid == 0) {
            int cum = 0, b = 255;
            for (; b > 0; b--) {
                cum += (int)hist[b];
                if (cum >= remaining) break;
            }
            if (cum < remaining) cum += (int)hist[0];
            s_rem = remaining - (cum - (int)hist[b]);
            s_prefix = prefix | ((unsigned)b << shift);
        }
        __syncthreads();
        prefix = s_prefix; remaining = s_rem;
        __syncthreads();
    }

    if (tid < NW) {
        unsigned gm = 0, em = 0;
        #pragma unroll 8
        for (int b = 0; b < 32; b++) {
            unsigned v = vals[tid * 32 + b];
            gm |= (v > prefix ? 1u : 0u) << b;
            em |= (v == prefix ? 1u : 0u) << b;
        }
        gtw[tid] = gm; eqw[tid] = em; wcnt[tid] = __popc(em);
    }
    __syncthreads();
    if (tid == 0) {
        unsigned run = 0;
        for (int w = 0; w < NW; w++) { psum[w] = run; run += wcnt[w]; }
    }
    __syncthreads();
    if (tid < NW) {
        unsigned em = eqw[tid], sel = 0;
        int rank = (int)psum[tid];
        while (em) {
            int b = __ffs(em) - 1;
            if (rank < remaining) sel |= 1u << b;
            rank++;
            em &= em - 1;
        }
        bits[tid] = gtw[tid] | sel;
    }
}

// ---------------- kernel D: tensor-core masked flash attention ----------------
// 128-row q tiles. smem: Q 0..32K, vb@32768, sb@33280,
// stages @34816: each 32K = K(16K) V(16K). total 100352.
#define SM_Q  0
#define SM_VB 32768
#define SM_SB 33280
#define SM_ST 34816
#define SM_STSZ 32768
#define FL_BYTES (SM_ST + 2 * SM_STSZ)

__device__ __forceinline__ void load_stage(unsigned st, size_t hb, int jb, int tid) {
    #pragma unroll
    for (int i = 0; i < 8; i++) {
        int e = tid + i * 256;          // 0..2047
        int arr = e >> 10;              // 0:K 1:V
        int x = e & 1023;
        int r = x >> 4, c = x & 15;
        unsigned off = (unsigned)(r * 256 + ((c ^ (r & 7)) << 4));
        const unsigned* src = (arr ? g_v : g_k) + hb + (size_t)(jb + r) * 64 + c * 4;
        cpa16(st + (unsigned)arr * 16384u + off, src);
    }
}

__global__ void __launch_bounds__(256, 1)
flash_mma_kernel(float* __restrict__ out) {
    extern __shared__ unsigned char smem[];
    const unsigned sb0 = (unsigned)__cvta_generic_to_shared(smem);
    unsigned* vbm = (unsigned*)(smem + SM_VB);
    unsigned* sbm = (unsigned*)(smem + SM_SB);

    int bid = blockIdx.x;
    int h   = bid & 7;
    int itb = 31 - (bid >> 3);          // heavy-first
    int tid = threadIdx.x, lane = tid & 31, w = tid >> 5;
    int g = lane >> 2, t = lane & 3;
    const int qr0 = w * 16;
    const int i0g = itb * 128;
    const int iA = i0g + qr0 + g;
    const int it2 = 2 * itb + 1;
    const size_t hb = (size_t)h * SEQ * 64;

    if (tid < NW)            vbm[tid]      = g_vbits[h * NW + tid];
    else if (tid < 2 * NW)   sbm[tid - NW] = g_sbits[h * NW + tid - NW];

    // Q tile (128 rows) + stage 0, one commit group
    #pragma unroll
    for (int i = 0; i < 8; i++) {
        int e = tid + i * 256;          // 0..2047 -> Q rows
        int r = e >> 4, c = e & 15;
        unsigned off = (unsigned)(r * 256 + ((c ^ (r & 7)) << 4));
        cpa16(sb0 + SM_Q + off, &g_q[hb + (size_t)(i0g + r) * 64 + c * 4]);
    }
    load_stage(sb0 + SM_ST, hb, 0, tid);
    cpa_commit();
    cpa_wait0();
    __syncthreads();

    int am = (lane >> 3) & 1, ar = lane & 7, ac = lane >> 4;

    // hoisted Q fragments (invariant across jt)
    unsigned Qh[8][4];
    #pragma unroll
    for (int ks = 0; ks < 8; ks++) {
        int row = qr0 + am * 8 + ar, ch = ks * 2 + ac;
        ldsm4(Qh[ks], sb0 + SM_Q + row * 256 + ((ch ^ (row & 7)) << 4));
    }

    float O[16][4];
    #pragma unroll
    for (int o = 0; o < 16; o++) { O[o][0]=0;O[o][1]=0;O[o][2]=0;O[o][3]=0; }
    float lg = 0.f, lg8 = 0.f;

    for (int jt = 0; jt <= it2; jt++) {
        if (jt > 0) { cpa_wait0(); __syncthreads(); }
        unsigned st = sb0 + SM_ST + (jt & 1) * SM_STSZ;
        if (jt < it2) {
            load_stage(sb0 + SM_ST + ((jt + 1) & 1) * SM_STSZ, hb, (jt + 1) * 64, tid);
            cpa_commit();
        }

        // ---- QK: S[16 rows][64 keys] per warp ----
        float S[8][4];
        #pragma unroll
        for (int n = 0; n < 8; n++) { S[n][0]=0;S[n][1]=0;S[n][2]=0;S[n][3]=0; }

        #pragma unroll
        for (int ks = 0; ks < 8; ks++) {
            #pragma unroll
            for (int kt = 0; kt < 4; kt++) {
                unsigned bh[4];
                int row = kt * 16 + am * 8 + ar, ch = ks * 2 + ac;
                ldsm4(bh, st + row * 256 + ((ch ^ (row & 7)) << 4));
                mma16(S[kt*2],   Qh[ks], bh[0], bh[2]);
                mma16(S[kt*2+1], Qh[ks], bh[1], bh[3]);
            }
        }

        // ---- mask + exp (max-free); round P to fp16, l from rounded p ----
        int jb = jt * 64;
        #pragma unroll
        for (int n = 0; n < 8; n++) {
            int cb = n * 8 + 2 * t;
            #pragma unroll
            for (int e = 0; e < 4; e++) {
                int roff = (e >> 1) * 8, b = e & 1;
                int j = jb + cb + b;
                int d = iA + roff - j;
                unsigned sbit = (d >= 0) ? ((sbm[d >> 5] >> (d & 31)) & 1u) : 0u;
                unsigned vbit = (vbm[j >> 5] >> (j & 31)) & 1u;
                bool ok = (d >= 0) && (vbit || sbit);
                float p = ok ? __expf(S[n][e]) : 0.f;
                p = __half2float(__float2half_rn(p));
                S[n][e] = p;
                if (e < 2) lg += p; else lg8 += p;
            }
        }

        // ---- PV (fp16 P x fp16 V) ----
        #pragma unroll
        for (int kp = 0; kp < 4; kp++) {
            unsigned aph[4];
            #pragma unroll
            for (int u = 0; u < 4; u++) {
                aph[u] = pk2h(S[kp*2 + (u>>1)][(u&1)*2], S[kp*2 + (u>>1)][(u&1)*2+1]);
            }
            #pragma unroll
            for (int n2 = 0; n2 < 8; n2++) {
                unsigned vh4[4];
                int row = kp * 16 + am * 8 + ar, ch = n2 * 2 + ac;
                ldsm4t(vh4, st + 16384 + row * 256 + ((ch ^ (row & 7)) << 4));
                mma16(O[n2*2],   aph, vh4[0], vh4[1]);
                mma16(O[n2*2+1], aph, vh4[2], vh4[3]);
            }
        }
    }

    // ---- epilogue: per-warp rows, no cross-warp combine ----
    lg  += __shfl_xor_sync(0xffffffffu, lg, 1);  lg  += __shfl_xor_sync(0xffffffffu, lg, 2);
    lg8 += __shfl_xor_sync(0xffffffffu, lg8, 1); lg8 += __shfl_xor_sync(0xffffffffu, lg8, 2);
    float inv0 = 1.0f / lg, inv1 = 1.0f / lg8;
    size_t ob = (size_t)h * SEQ * DH;
    int r0 = i0g + qr0 + g, r1 = r0 + 8;
    #pragma unroll
    for (int o = 0; o < 16; o++) {
        *(float2*)&out[ob + (size_t)r0 * DH + o * 8 + 2 * t] =
            make_float2(O[o][0] * inv0, O[o][1] * inv0);
        *(float2*)&out[ob + (size_t)r1 * DH + o * 8 + 2 * t] =
            make_float2(O[o][2] * inv1, O[o][3] * inv1);
    }
}

// ---------------- launch ----------------
extern "C" void kernel_launch(void* const* d_in, const int* in_sizes, int n_in,
                              void* d_out, int out_size) {
    const float* q = (const float*)d_in[0];
    const float* k = (const float*)d_in[1];
    const float* v = (const float*)d_in[2];
    float* out = (float*)d_out;

    prep_kernel<<<(NPAIR + 255) / 256, 256>>>(q, k, v);

    int psm = (64 * QS_STRIDE + 128 * 128) * 4;
    cudaFuncSetAttribute(pattern_kernel, cudaFuncAttributeMaxDynamicSharedMemorySize, psm);
    pattern_kernel<<<dim3(SEQ / 128, NH), 256, psm>>>(q, k);
    rowsum_kernel<<<NH * LQ, 128>>>();
    reduce_kernel<<<dim3(NH, SEQ / 256), 256>>>();
    topk_kernel<<<dim3(2, NH), 256>>>();

    cudaFuncSetAttribute(flash_mma_kernel, cudaFuncAttributeMaxDynamicSharedMemorySize, FL_BYTES);
    flash_mma_kernel<<<32 * NH, 256, FL_BYTES>>>(out);
}